// round 7
// baseline (speedup 1.0000x reference)
#include <cuda_runtime.h>

#define Tn   2048
#define Bn   512
#define INn  27
#define Hn   64
#define OUTn 26
#define Gn   256   // 4*H

// 256 MB scratch for h_new[t][b][h] (allowed: __device__ global, no cudaMalloc)
__device__ float g_hall[Tn * Bn * Hn];

// ---- packed f32x2 helpers (Blackwell FFMA2) ----
__device__ __forceinline__ unsigned long long pack2(float lo, float hi) {
    unsigned long long r;
    asm("mov.b64 %0, {%1, %2};" : "=l"(r) : "f"(lo), "f"(hi));
    return r;
}
__device__ __forceinline__ void unpack2(unsigned long long v, float& lo, float& hi) {
    asm("mov.b64 {%0, %1}, %2;" : "=f"(lo), "=f"(hi) : "l"(v));
}
__device__ __forceinline__ unsigned long long ffma2(unsigned long long a,
                                                    unsigned long long b,
                                                    unsigned long long c) {
    unsigned long long d;
    asm("fma.rn.f32x2 %0, %1, %2, %3;" : "=l"(d) : "l"(a), "l"(b), "l"(c));
    return d;
}

__device__ __forceinline__ float fast_sigmoid(float x) {
    return __fdividef(1.0f, 1.0f + __expf(-x));
}
__device__ __forceinline__ float fast_tanh(float x) {
    float e = __expf(2.0f * x);
    return 1.0f - __fdividef(2.0f, e + 1.0f);
}

// ============================================================================
// Stage 1: 512 independent LSTMs. One CTA per batch element, one gate per
// thread, weights register-resident, h broadcast from SMEM.
// __launch_bounds__(256, 2): cap regs at 128 so TWO CTAs co-reside per SM.
// Grid 512 then runs in 2 waves instead of 4; the co-resident CTA's issue
// traffic hides in this CTA's barrier/LDS-latency stalls.
// ============================================================================
__global__ __launch_bounds__(256, 2)
void lstm_kernel(const float* __restrict__ x,      // [T,B,IN]
                 const float* __restrict__ W_ih,   // [256,27]
                 const float* __restrict__ W_hh,   // [256,64]
                 const float* __restrict__ b_ih,   // [256]
                 const float* __restrict__ b_hh)   // [256]
{
    const int b = blockIdx.x;      // batch element
    const int g = threadIdx.x;     // gate id 0..255

    __shared__ __align__(16) float h_s[Hn];        // current hidden state
    __shared__ __align__(16) float gates_s[Gn];    // activated gates
    __shared__ __align__(16) float x_s[2][28];     // double-buffered x_t (pad 28)

    // ---- load this gate's weights into registers, packed as f32x2 ----
    unsigned long long whh[32];         // 64 W_hh values
    unsigned long long wih[14];         // 27 W_ih values (+1 zero pad)
    {
        const float* wr = W_hh + g * Hn;
#pragma unroll
        for (int k = 0; k < 32; k++) whh[k] = pack2(wr[2*k], wr[2*k+1]);
        const float* wr2 = W_ih + g * INn;
#pragma unroll
        for (int k = 0; k < 14; k++) {
            float lo = wr2[2*k];
            float hi = (2*k + 1 < INn) ? wr2[2*k+1] : 0.0f;
            wih[k] = pack2(lo, hi);
        }
    }
    const float bias  = b_ih[g] + b_hh[g];
    const int   gtype = g >> 6;   // 0:i  1:f  2:g(tanh)  3:o

    float c_reg = 0.0f;           // cell state, owned by threads 0..63

    // ---- init shared state ----
    if (g < Hn)  h_s[g] = 0.0f;
    if (g == 0) { x_s[0][27] = 0.0f; x_s[1][27] = 0.0f; }
    if (g < INn) x_s[0][g] = x[b * INn + g];   // t = 0
    __syncthreads();

    // incremental global store address (save per-step IMADs)
    float* hall_p = g_hall + b * Hn + (g & 63);

    int buf = 0;
    for (int t = 0; t < Tn; t++) {
        // prefetch x for t+1 early (LDG latency hidden behind gate compute)
        float xr = 0.0f;
        if (g >= 64 && g < 64 + INn && (t + 1) < Tn)
            xr = x[((t + 1) * Bn + b) * INn + (g - 64)];

        // ---- gate pre-activation: h.W_hh + x.W_ih (packed f32x2 FMAs) ----
        unsigned long long a0 = 0ull, a1 = 0ull;  // {0.f,0.f}
        const ulonglong2* hp = (const ulonglong2*)h_s;   // LDS.128
#pragma unroll
        for (int k = 0; k < 16; k++) {
            ulonglong2 hv = hp[k];
            a0 = ffma2(hv.x, whh[2*k],     a0);
            a1 = ffma2(hv.y, whh[2*k + 1], a1);
        }
        const ulonglong2* xp = (const ulonglong2*)x_s[buf];  // LDS.128
#pragma unroll
        for (int k = 0; k < 7; k++) {
            ulonglong2 xv = xp[k];
            a0 = ffma2(xv.x, wih[2*k],     a0);
            a1 = ffma2(xv.y, wih[2*k + 1], a1);
        }
        float l0, h0, l1, h1;
        unpack2(a0, l0, h0);
        unpack2(a1, l1, h1);
        float acc = bias + ((l0 + h0) + (l1 + h1));

        float act = (gtype == 2) ? fast_tanh(acc) : fast_sigmoid(acc);
        gates_s[g] = act;
        __syncthreads();

        // ---- cell/hidden update (threads 0..63) + x stage-in (64..90) ----
        if (g < Hn) {
            float iv = gates_s[g];
            float fv = gates_s[Hn + g];
            float gv = gates_s[2 * Hn + g];
            float ov = gates_s[3 * Hn + g];
            c_reg = fv * c_reg + iv * gv;
            float hv = ov * fast_tanh(c_reg);
            h_s[g] = hv;
            *hall_p = hv;
        } else if (g < 64 + INn) {
            x_s[buf ^ 1][g - 64] = xr;
        }
        __syncthreads();
        hall_p += Bn * Hn;
        buf ^= 1;
    }
}

// ============================================================================
// Stage 2: per-timestep BatchNorm (batch stats) -> LockedDropout -> max over
// batch -> FC with prev_guess concat. One CTA per timestep.
// The 128 KB [B][H] tile is cached in dynamic smem during pass 1 so pass 2
// never touches DRAM again (halves stage-2 HBM traffic).
// ============================================================================
__global__ __launch_bounds__(256)
void bn_pool_fc_kernel(const float* __restrict__ pg,     // [T,OUT]
                       const float* __restrict__ gamma,  // [H]
                       const float* __restrict__ beta,   // [H]
                       const float* __restrict__ W_fc,   // [OUT, H+OUT]
                       const float* __restrict__ b_fc,   // [OUT]
                       const float* __restrict__ mask,   // [B,H]
                       float* __restrict__ out)          // [T,1,OUT]
{
    const int t   = blockIdx.x;
    const int tid = threadIdx.x;
    const int h   = tid & 63;
    const int grp = tid >> 6;     // 4 groups over batch

    const float* base = g_hall + (size_t)t * Bn * Hn;

    extern __shared__ float tile[];          // [Bn][Hn] = 128 KB
    __shared__ float redA[4][Hn];
    __shared__ float redB[4][Hn];
    __shared__ float scale_s[Hn], shift_s[Hn];
    __shared__ float pooled[Hn];

    // pass 1: sum / sumsq over batch, caching values in smem
    float s = 0.0f, ss = 0.0f;
#pragma unroll 8
    for (int bb = grp; bb < Bn; bb += 4) {
        float v = base[bb * Hn + h];
        tile[bb * Hn + h] = v;
        s += v;
        ss += v * v;
    }
    redA[grp][h] = s;
    redB[grp][h] = ss;
    __syncthreads();

    if (tid < Hn) {
        float sum = redA[0][tid] + redA[1][tid] + redA[2][tid] + redA[3][tid];
        float sq  = redB[0][tid] + redB[1][tid] + redB[2][tid] + redB[3][tid];
        float mean = sum * (1.0f / Bn);
        float var  = sq * (1.0f / Bn) - mean * mean;
        float rstd = rsqrtf(var + 1e-5f);
        float sc   = rstd * gamma[tid];
        scale_s[tid] = sc;
        shift_s[tid] = beta[tid] - mean * sc;
    }
    __syncthreads();

    // pass 2: masked affine + max over batch (reads from smem tile; mask is
    // 128 KB total -> L2-resident across the grid)
    float sc = scale_s[h], sh = shift_s[h];
    float mx = -3.402823466e38f;
#pragma unroll 8
    for (int bb = grp; bb < Bn; bb += 4) {
        float v  = tile[bb * Hn + h];
        float hd = (v * sc + sh) * mask[bb * Hn + h];
        mx = fmaxf(mx, hd);
    }
    redA[grp][h] = mx;
    __syncthreads();

    if (tid < Hn)
        pooled[tid] = fmaxf(fmaxf(redA[0][tid], redA[1][tid]),
                            fmaxf(redA[2][tid], redA[3][tid]));
    __syncthreads();

    // FC: y[t][o] = [pooled, pg_t] . W_fc[o] + b_fc[o]
    if (tid < OUTn) {
        const float* w = W_fc + tid * (Hn + OUTn);
        float acc = b_fc[tid];
#pragma unroll
        for (int k = 0; k < Hn; k++) acc += pooled[k] * w[k];
#pragma unroll
        for (int k = 0; k < OUTn; k++) acc += pg[t * OUTn + k] * w[Hn + k];
        out[t * OUTn + tid] = acc;
    }
}

// ============================================================================
// Launch
// ============================================================================
extern "C" void kernel_launch(void* const* d_in, const int* in_sizes, int n_in,
                              void* d_out, int out_size) {
    const float* x      = (const float*)d_in[0];   // obscure_word [T,B,IN]
    const float* pg     = (const float*)d_in[1];   // prev_guess   [T,OUT]
    const float* W_ih   = (const float*)d_in[2];   // [4H,IN]
    const float* W_hh   = (const float*)d_in[3];   // [4H,H]
    const float* b_ih   = (const float*)d_in[4];   // [4H]
    const float* b_hh   = (const float*)d_in[5];   // [4H]
    const float* gamma  = (const float*)d_in[6];   // [H]
    const float* beta   = (const float*)d_in[7];   // [H]
    const float* W_fc   = (const float*)d_in[8];   // [OUT,H+OUT]
    const float* b_fc   = (const float*)d_in[9];   // [OUT]
    const float* dmask  = (const float*)d_in[10];  // [B,H]
    float* out = (float*)d_out;

    // 128 KB dynamic smem for the stage-2 batch tile (idempotent, host-side,
    // not a stream op -> safe under graph capture)
    static int smem_set = 0;
    if (!smem_set) {
        cudaFuncSetAttribute(bn_pool_fc_kernel,
                             cudaFuncAttributeMaxDynamicSharedMemorySize,
                             Bn * Hn * (int)sizeof(float));
        smem_set = 1;
    }

    lstm_kernel<<<Bn, 256>>>(x, W_ih, W_hh, b_ih, b_hh);
    bn_pool_fc_kernel<<<Tn, 256, Bn * Hn * sizeof(float)>>>(
        pg, gamma, beta, W_fc, b_fc, dmask, out);
}

// round 8
// speedup vs baseline: 1.1433x; 1.1433x over previous
#include <cuda_runtime.h>
#include <float.h>

#define Tn   2048
#define Bn   512
#define INn  27
#define Hn   64
#define OUTn 26
#define Gn   256   // 4*H
#define BPC  4     // batches per CTA

// 256 MB scratch for h_new[t][b][h]
__device__ float g_hall[Tn * Bn * Hn];

// ---- packed f32x2 helpers (Blackwell FFMA2) ----
__device__ __forceinline__ unsigned long long pack2(float lo, float hi) {
    unsigned long long r;
    asm("mov.b64 %0, {%1, %2};" : "=l"(r) : "f"(lo), "f"(hi));
    return r;
}
__device__ __forceinline__ void unpack2(unsigned long long v, float& lo, float& hi) {
    asm("mov.b64 {%0, %1}, %2;" : "=f"(lo), "=f"(hi) : "l"(v));
}
__device__ __forceinline__ unsigned long long ffma2(unsigned long long a,
                                                    unsigned long long b,
                                                    unsigned long long c) {
    unsigned long long d;
    asm("fma.rn.f32x2 %0, %1, %2, %3;" : "=l"(d) : "l"(a), "l"(b), "l"(c));
    return d;
}

__device__ __forceinline__ float sigmoidf_(float x) {
    return __fdividef(1.0f, 1.0f + __expf(-x));
}
__device__ __forceinline__ float tanhf_(float x) {
    // tanh(x) = 2*sigmoid(2x) - 1  (robust at extremes)
    return 2.0f * __fdividef(1.0f, 1.0f + __expf(-2.0f * x)) - 1.0f;
}

// ============================================================================
// Stage 1: 512 LSTMs, 4 batches/CTA -> grid 128 (SINGLE wave on 148 SMs).
// 512 threads; thread = 1 gate x 2 batches (weights shared in regs).
// Lane layout per warp: warp w: pair = w>>3 (batches 2p,2p+1),
//   hgroup = w&7; lane l: h_loc = hgroup*8 + (l&7), gate_type = l>>3.
// i/f/g/o for one h live in lanes l, l^8(+), ... -> gathered by 3 shfl.idx,
// so only ONE __syncthreads per step (h_s double-buffered).
// ============================================================================
__global__ __launch_bounds__(512, 1)
void lstm_kernel(const float* __restrict__ x,      // [T,B,IN]
                 const float* __restrict__ W_ih,   // [256,27]
                 const float* __restrict__ W_hh,   // [256,64]
                 const float* __restrict__ b_ih,   // [256]
                 const float* __restrict__ b_hh)   // [256]
{
    const int tid  = threadIdx.x;
    const int lane = tid & 31;
    const int warp = tid >> 5;
    const int pair = warp >> 3;              // 0 or 1
    const int hloc = ((warp & 7) << 3) | (lane & 7);
    const int gtyp = lane >> 3;              // 0:i 1:f 2:g 3:o
    const int g    = gtyp * 64 + hloc;       // gate row

    const int bl0 = 2 * pair;                // local batches
    const int bl1 = 2 * pair + 1;
    const int bg0 = blockIdx.x * BPC + bl0;  // global batches
    const int bg1 = bg0 + 1;

    __shared__ __align__(16) float h_s[2][BPC][Hn];   // double-buffered hidden
    __shared__ __align__(16) float x_s[2][BPC][32];   // double-buffered x (pad 32)

    // ---- weights -> registers (f32x2 packed) ----
    unsigned long long whh[32];
    unsigned long long wih[14];
    {
        const float* wr = W_hh + g * Hn;
#pragma unroll
        for (int k = 0; k < 32; k++) whh[k] = pack2(wr[2*k], wr[2*k+1]);
        const float* wr2 = W_ih + g * INn;
#pragma unroll
        for (int k = 0; k < 13; k++) wih[k] = pack2(wr2[2*k], wr2[2*k+1]);
        wih[13] = pack2(wr2[26], 0.0f);
    }
    const float bias = b_ih[g] + b_hh[g];
    // uniform activation path: act = A*sigmoid(S*pre) + C  (type2 == tanh)
    const float Sg = (gtyp == 2) ? 2.0f : 1.0f;
    const float Ag = (gtyp == 2) ? 2.0f : 1.0f;
    const float Cg = (gtyp == 2) ? -1.0f : 0.0f;

    float c0 = 0.0f, c1 = 0.0f;   // cell state (consistent redundant copies)

    // ---- x prefetch assignment: 108 values = 4 batches x 27 cols ----
    const bool do_x = tid < BPC * INn;
    const int  pxb  = tid / INn;             // local batch 0..3
    const int  pxc  = tid - pxb * INn;       // col 0..26
    const float* xp = x + ((size_t)Bn + (blockIdx.x * BPC + pxb)) * INn + pxc; // t=1

    // ---- init smem ----
    if (tid < BPC * Hn) ((float*)h_s[0])[tid] = 0.0f;
    if (tid < 2 * BPC) { x_s[0][tid & 3][27] = 0.0f; x_s[1][tid & 3][27] = 0.0f; }
    if (do_x) x_s[0][pxb][pxc] = x[(size_t)(blockIdx.x * BPC + pxb) * INn + pxc];
    __syncthreads();

    float* hall0 = g_hall + (size_t)bg0 * Hn + hloc;
    float* hall1 = g_hall + (size_t)bg1 * Hn + hloc;

    int buf = 0;
    for (int t = 0; t < Tn; t++) {
        // prefetch x for t+1
        float xr = 0.0f;
        if (do_x && (t + 1) < Tn) xr = *xp;
        xp += (size_t)Bn * INn;

        // ---- gate pre-activations for both batches ----
        unsigned long long a00 = 0ull, a01 = 0ull, a10 = 0ull, a11 = 0ull;
        const ulonglong2* hp0 = (const ulonglong2*)h_s[buf][bl0];
        const ulonglong2* hp1 = (const ulonglong2*)h_s[buf][bl1];
#pragma unroll
        for (int k = 0; k < 16; k++) {
            ulonglong2 hv0 = hp0[k];
            ulonglong2 hv1 = hp1[k];
            a00 = ffma2(hv0.x, whh[2*k],     a00);
            a01 = ffma2(hv0.y, whh[2*k + 1], a01);
            a10 = ffma2(hv1.x, whh[2*k],     a10);
            a11 = ffma2(hv1.y, whh[2*k + 1], a11);
        }
        const ulonglong2* xp0 = (const ulonglong2*)x_s[buf][bl0];
        const ulonglong2* xp1 = (const ulonglong2*)x_s[buf][bl1];
#pragma unroll
        for (int k = 0; k < 7; k++) {
            ulonglong2 xv0 = xp0[k];
            ulonglong2 xv1 = xp1[k];
            a00 = ffma2(xv0.x, wih[2*k],     a00);
            a01 = ffma2(xv0.y, wih[2*k + 1], a01);
            a10 = ffma2(xv1.x, wih[2*k],     a10);
            a11 = ffma2(xv1.y, wih[2*k + 1], a11);
        }
        float p0, q0, r0, s0, p1, q1, r1, s1;
        unpack2(a00, p0, q0); unpack2(a01, r0, s0);
        unpack2(a10, p1, q1); unpack2(a11, r1, s1);
        float acc0 = bias + ((p0 + q0) + (r0 + s0));
        float acc1 = bias + ((p1 + q1) + (r1 + s1));

        float act0 = Ag * sigmoidf_(Sg * acc0) + Cg;
        float act1 = Ag * sigmoidf_(Sg * acc1) + Cg;

        // ---- gather i,f,g,o for this h via shfl (all lanes get copies) ----
        const int base = lane & 7;
        float iv0 = __shfl_sync(0xffffffffu, act0, base);
        float fv0 = __shfl_sync(0xffffffffu, act0, base + 8);
        float gv0 = __shfl_sync(0xffffffffu, act0, base + 16);
        float ov0 = __shfl_sync(0xffffffffu, act0, base + 24);
        float iv1 = __shfl_sync(0xffffffffu, act1, base);
        float fv1 = __shfl_sync(0xffffffffu, act1, base + 8);
        float gv1 = __shfl_sync(0xffffffffu, act1, base + 16);
        float ov1 = __shfl_sync(0xffffffffu, act1, base + 24);

        // ---- cell/hidden update (redundant consistent copies in all lanes) ----
        c0 = fv0 * c0 + iv0 * gv0;
        c1 = fv1 * c1 + iv1 * gv1;
        float hv0 = ov0 * tanhf_(c0);
        float hv1 = ov1 * tanhf_(c1);

        if (lane < 8) {                       // one writer per (h, batch)
            h_s[buf ^ 1][bl0][hloc] = hv0;
            h_s[buf ^ 1][bl1][hloc] = hv1;
            *hall0 = hv0;
            *hall1 = hv1;
        }
        if (do_x) x_s[buf ^ 1][pxb][pxc] = xr;

        __syncthreads();
        hall0 += (size_t)Bn * Hn;
        hall1 += (size_t)Bn * Hn;
        buf ^= 1;
    }
}

// ============================================================================
// Stage 2: single-pass BN-stats + masked-extrema + pool + FC, one CTA per t.
// Exploits mask in {0, 1/(1-p)}: max_b m*(v*sc+sh) = m * ((sc>=0?vmax:vmin)*sc+sh)
// over masked-in b, vs 0 if any b is masked out. One 256MB read total.
// ============================================================================
__global__ __launch_bounds__(256)
void bn_pool_fc_kernel(const float* __restrict__ pg,     // [T,OUT]
                       const float* __restrict__ gamma,  // [H]
                       const float* __restrict__ beta,   // [H]
                       const float* __restrict__ W_fc,   // [OUT, H+OUT]
                       const float* __restrict__ b_fc,   // [OUT]
                       const float* __restrict__ mask,   // [B,H]
                       float* __restrict__ out)          // [T,1,OUT]
{
    const int t   = blockIdx.x;
    const int tid = threadIdx.x;
    const int h   = tid & 63;
    const int grp = tid >> 6;     // 4 groups over batch

    const float* base = g_hall + (size_t)t * Bn * Hn;

    __shared__ float rS[4][Hn], rQ[4][Hn], rMx[4][Hn], rMn[4][Hn],
                     rMv[4][Hn], rZ[4][Hn];
    __shared__ float pooled[Hn];

    float s = 0.0f, ss = 0.0f;
    float vmx = -FLT_MAX, vmn = FLT_MAX, mv = 0.0f, anyz = 0.0f;
#pragma unroll 4
    for (int bb = grp; bb < Bn; bb += 4) {
        float v = base[bb * Hn + h];
        float m = mask[bb * Hn + h];
        s  += v;
        ss += v * v;
        if (m > 0.0f) {
            vmx = fmaxf(vmx, v);
            vmn = fminf(vmn, v);
            mv  = fmaxf(mv, m);
        } else {
            anyz = 1.0f;
        }
    }
    rS[grp][h] = s;   rQ[grp][h] = ss;
    rMx[grp][h] = vmx; rMn[grp][h] = vmn;
    rMv[grp][h] = mv;  rZ[grp][h] = anyz;
    __syncthreads();

    if (tid < Hn) {
        float sum = rS[0][tid] + rS[1][tid] + rS[2][tid] + rS[3][tid];
        float sq  = rQ[0][tid] + rQ[1][tid] + rQ[2][tid] + rQ[3][tid];
        float mx  = fmaxf(fmaxf(rMx[0][tid], rMx[1][tid]),
                          fmaxf(rMx[2][tid], rMx[3][tid]));
        float mn  = fminf(fminf(rMn[0][tid], rMn[1][tid]),
                          fminf(rMn[2][tid], rMn[3][tid]));
        float m   = fmaxf(fmaxf(rMv[0][tid], rMv[1][tid]),
                          fmaxf(rMv[2][tid], rMv[3][tid]));
        float z   = fmaxf(fmaxf(rZ[0][tid], rZ[1][tid]),
                          fmaxf(rZ[2][tid], rZ[3][tid]));
        float mean = sum * (1.0f / Bn);
        float var  = sq * (1.0f / Bn) - mean * mean;
        float rstd = rsqrtf(var + 1e-5f);
        float sc   = rstd * gamma[tid];
        float sh   = beta[tid] - mean * sc;

        float p;
        if (mx == -FLT_MAX) {
            p = 0.0f;                         // every b masked out
        } else {
            float vstar = (sc >= 0.0f) ? mx : mn;
            p = m * (vstar * sc + sh);
            if (z > 0.0f) p = fmaxf(p, 0.0f); // zero candidates present
        }
        pooled[tid] = p;
    }
    __syncthreads();

    // FC: y[t][o] = [pooled, pg_t] . W_fc[o] + b_fc[o]
    if (tid < OUTn) {
        const float* w = W_fc + tid * (Hn + OUTn);
        float acc = b_fc[tid];
#pragma unroll
        for (int k = 0; k < Hn; k++) acc += pooled[k] * w[k];
#pragma unroll
        for (int k = 0; k < OUTn; k++) acc += pg[t * OUTn + k] * w[Hn + k];
        out[t * OUTn + tid] = acc;
    }
}

// ============================================================================
// Launch
// ============================================================================
extern "C" void kernel_launch(void* const* d_in, const int* in_sizes, int n_in,
                              void* d_out, int out_size) {
    const float* x      = (const float*)d_in[0];
    const float* pg     = (const float*)d_in[1];
    const float* W_ih   = (const float*)d_in[2];
    const float* W_hh   = (const float*)d_in[3];
    const float* b_ih   = (const float*)d_in[4];
    const float* b_hh   = (const float*)d_in[5];
    const float* gamma  = (const float*)d_in[6];
    const float* beta   = (const float*)d_in[7];
    const float* W_fc   = (const float*)d_in[8];
    const float* b_fc   = (const float*)d_in[9];
    const float* dmask  = (const float*)d_in[10];
    float* out = (float*)d_out;

    lstm_kernel<<<Bn / BPC, 512>>>(x, W_ih, W_hh, b_ih, b_hh);
    bn_pool_fc_kernel<<<Tn, 256>>>(pg, gamma, beta, W_fc, b_fc, dmask, out);
}

// round 9
// speedup vs baseline: 1.4132x; 1.2361x over previous
#include <cuda_runtime.h>
#include <float.h>

#define Tn   2048
#define Bn   512
#define INn  27
#define Hn   64
#define OUTn 26
#define Gn   256   // 4*H
#define BPC  4     // batches per CTA in stage 1

// scratch: h history (256 MB) + precomputed input-gate preactivations (1 GiB)
__device__ float g_hall[Tn * Bn * Hn];
__device__ float g_xw[(size_t)Tn * Bn * Gn];

// ---- packed f32x2 helpers (Blackwell FFMA2) ----
__device__ __forceinline__ unsigned long long pack2(float lo, float hi) {
    unsigned long long r;
    asm("mov.b64 %0, {%1, %2};" : "=l"(r) : "f"(lo), "f"(hi));
    return r;
}
__device__ __forceinline__ void unpack2(unsigned long long v, float& lo, float& hi) {
    asm("mov.b64 {%0, %1}, %2;" : "=f"(lo), "=f"(hi) : "l"(v));
}
__device__ __forceinline__ unsigned long long ffma2(unsigned long long a,
                                                    unsigned long long b,
                                                    unsigned long long c) {
    unsigned long long d;
    asm("fma.rn.f32x2 %0, %1, %2, %3;" : "=l"(d) : "l"(a), "l"(b), "l"(c));
    return d;
}
__device__ __forceinline__ float ex2f(float x) {
    float y; asm("ex2.approx.f32 %0, %1;" : "=f"(y) : "f"(x)); return y;
}
__device__ __forceinline__ float rcpf(float x) {
    float y; asm("rcp.approx.f32 %0, %1;" : "=f"(y) : "f"(x)); return y;
}

// ============================================================================
// Kernel 0: xw[t][b][g'] = x[t,b,:] . W_ih[g,:] + b_ih[g] + b_hh[g]
// g' is permuted to the stage-1 lane order: tid = hg*32 + gt*8 + h7 where
// g = gt*64 + hg*8 + h7 -> stage-1 warp (hg) reads 128B contiguous per batch.
// One CTA per t; f32x2 over batch pairs; W row register-resident.
// ============================================================================
__global__ __launch_bounds__(256)
void xw_kernel(const float* __restrict__ x,      // [T,B,IN]
               const float* __restrict__ W_ih,   // [256,27]
               const float* __restrict__ b_ih,
               const float* __restrict__ b_hh)
{
    const int t   = blockIdx.x;
    const int tid = threadIdx.x;
    const int gt  = (tid >> 3) & 3;
    const int hg  = tid >> 5;
    const int h7  = tid & 7;
    const int g   = gt * 64 + hg * 8 + h7;

    unsigned long long wp[27];
    {
        const float* wr = W_ih + g * INn;
#pragma unroll
        for (int k = 0; k < 27; k++) { float w = wr[k]; wp[k] = pack2(w, w); }
    }
    const float bias = b_ih[g] + b_hh[g];
    const unsigned long long bias2 = pack2(bias, bias);

    __shared__ unsigned long long xs[8 * 27];   // 8 batch-pairs x 27 cols
    float* outb = g_xw + (size_t)t * Bn * Gn;

    for (int bb = 0; bb < Bn; bb += 16) {
        __syncthreads();
        if (tid < 216) {
            int p = tid / 27, k = tid - p * 27;
            size_t a = ((size_t)t * Bn + bb + 2 * p) * INn + k;
            xs[tid] = pack2(x[a], x[a + INn]);
        }
        __syncthreads();
#pragma unroll
        for (int p = 0; p < 8; p++) {
            unsigned long long acc = bias2;
#pragma unroll
            for (int k = 0; k < 27; k++) acc = ffma2(xs[p * 27 + k], wp[k], acc);
            float lo, hi; unpack2(acc, lo, hi);
            outb[(size_t)(bb + 2 * p)     * Gn + tid] = lo;
            outb[(size_t)(bb + 2 * p + 1) * Gn + tid] = hi;
        }
    }
}

// ============================================================================
// Stage 1: 512 LSTMs, 4 batches/CTA -> grid 128 (single wave).
// Thread = 1 gate x 2 batches; W_hh register-resident (64 regs), x-part read
// from g_xw (2 coalesced LDG/step, prefetched). Lanes 0-15 uniquely own one
// (h, batch) for the cell update (no redundant tanh). One barrier/step via
// double-buffered h_s. ~100 live regs -> no spill at the 128 cap.
// ============================================================================
__global__ __launch_bounds__(512, 1)
void lstm_kernel(const float* __restrict__ W_hh)   // [256,64]
{
    const int tid  = threadIdx.x;
    const int lane = tid & 31;
    const int warp = tid >> 5;
    const int pair = warp >> 3;               // 0 or 1
    const int hg   = warp & 7;
    const int hloc = hg * 8 + (lane & 7);
    const int gtyp = lane >> 3;               // 0:i 1:f 2:g 3:o
    const int g    = gtyp * 64 + hloc;

    const int bl0 = 2 * pair;
    const int bg0 = blockIdx.x * BPC + bl0;

    __shared__ __align__(16) float h_s[2][BPC][Hn];

    // W_hh row -> registers (f32x2)
    unsigned long long whh[32];
    {
        const float* wr = W_hh + g * Hn;
#pragma unroll
        for (int k = 0; k < 32; k++) whh[k] = pack2(wr[2 * k], wr[2 * k + 1]);
    }

    // act = A * rcp(1 + ex2(K*pre)) + C   (gtyp2: tanh = 2*sigm(2x)-1)
    const float K = (gtyp == 2) ? -2.8853900817779268f : -1.4426950408889634f;
    const float A = (gtyp == 2) ?  2.0f : 1.0f;
    const float C = (gtyp == 2) ? -1.0f : 0.0f;

    float c = 0.0f;

    // xw pointer: per warp 128B contiguous per batch
    const float* xwp = g_xw + (size_t)bg0 * Gn + hg * 32 + lane;
    // h-history pointer (owner lanes 0-15)
    const int bsel = (lane >> 3) & 1;
    float* hallp = g_hall + (size_t)(bg0 + bsel) * Hn + hloc;

    if (tid < BPC * Hn) ((float*)h_s[0])[tid] = 0.0f;

    float xr0 = xwp[0], xr1 = xwp[Gn];
    xwp += (size_t)Bn * Gn;
    __syncthreads();

    int buf = 0;
    for (int t = 0; t < Tn; t++) {
        // prefetch xw for t+1
        float nx0 = 0.0f, nx1 = 0.0f;
        if (t + 1 < Tn) { nx0 = xwp[0]; nx1 = xwp[Gn]; }
        xwp += (size_t)Bn * Gn;

        // gate pre-activation: h . W_hh (x-part + biases already in xr)
        unsigned long long a00 = 0ull, a01 = 0ull, a10 = 0ull, a11 = 0ull;
        const ulonglong2* hp0 = (const ulonglong2*)h_s[buf][bl0];
        const ulonglong2* hp1 = (const ulonglong2*)h_s[buf][bl0 + 1];
#pragma unroll
        for (int k = 0; k < 16; k++) {
            ulonglong2 h0 = hp0[k];
            ulonglong2 h1 = hp1[k];
            a00 = ffma2(h0.x, whh[2 * k],     a00);
            a01 = ffma2(h0.y, whh[2 * k + 1], a01);
            a10 = ffma2(h1.x, whh[2 * k],     a10);
            a11 = ffma2(h1.y, whh[2 * k + 1], a11);
        }
        float p0, q0, r0, s0, p1, q1, r1, s1;
        unpack2(a00, p0, q0); unpack2(a01, r0, s0);
        unpack2(a10, p1, q1); unpack2(a11, r1, s1);
        float acc0 = xr0 + ((p0 + q0) + (r0 + s0));
        float acc1 = xr1 + ((p1 + q1) + (r1 + s1));
        xr0 = nx0; xr1 = nx1;

        float act0 = fmaf(A, rcpf(1.0f + ex2f(K * acc0)), C);
        float act1 = fmaf(A, rcpf(1.0f + ex2f(K * acc1)), C);

        // gather i,f,g,o for this lane's (h, batch)
        const int base = lane & 7;
        float i0 = __shfl_sync(0xffffffffu, act0, base);
        float i1 = __shfl_sync(0xffffffffu, act1, base);
        float f0 = __shfl_sync(0xffffffffu, act0, base + 8);
        float f1 = __shfl_sync(0xffffffffu, act1, base + 8);
        float g0 = __shfl_sync(0xffffffffu, act0, base + 16);
        float g1 = __shfl_sync(0xffffffffu, act1, base + 16);
        float o0 = __shfl_sync(0xffffffffu, act0, base + 24);
        float o1 = __shfl_sync(0xffffffffu, act1, base + 24);
        const bool sel = (lane & 8) != 0;
        float iv = sel ? i1 : i0;
        float fv = sel ? f1 : f0;
        float gv = sel ? g1 : g0;
        float ov = sel ? o1 : o0;

        // cell/hidden update: lanes 0-15 own (h = hloc, batch = bl0+bsel)
        c = fmaf(fv, c, iv * gv);
        float th = fmaf(2.0f, rcpf(1.0f + ex2f(-2.8853900817779268f * c)), -1.0f);
        float hv = ov * th;
        if (lane < 16) {
            h_s[buf ^ 1][bl0 + bsel][hloc] = hv;
            *hallp = hv;
        }
        hallp += (size_t)Bn * Hn;
        __syncthreads();
        buf ^= 1;
    }
}

// ============================================================================
// Stage 2 (unchanged from R8, 70.9us): single-pass BN-stats + masked-extrema
// + pool + FC, one CTA per timestep.
// ============================================================================
__global__ __launch_bounds__(256)
void bn_pool_fc_kernel(const float* __restrict__ pg,     // [T,OUT]
                       const float* __restrict__ gamma,  // [H]
                       const float* __restrict__ beta,   // [H]
                       const float* __restrict__ W_fc,   // [OUT, H+OUT]
                       const float* __restrict__ b_fc,   // [OUT]
                       const float* __restrict__ mask,   // [B,H]
                       float* __restrict__ out)          // [T,1,OUT]
{
    const int t   = blockIdx.x;
    const int tid = threadIdx.x;
    const int h   = tid & 63;
    const int grp = tid >> 6;

    const float* base = g_hall + (size_t)t * Bn * Hn;

    __shared__ float rS[4][Hn], rQ[4][Hn], rMx[4][Hn], rMn[4][Hn],
                     rMv[4][Hn], rZ[4][Hn];
    __shared__ float pooled[Hn];

    float s = 0.0f, ss = 0.0f;
    float vmx = -FLT_MAX, vmn = FLT_MAX, mv = 0.0f, anyz = 0.0f;
#pragma unroll 4
    for (int bb = grp; bb < Bn; bb += 4) {
        float v = base[bb * Hn + h];
        float m = mask[bb * Hn + h];
        s  += v;
        ss += v * v;
        if (m > 0.0f) {
            vmx = fmaxf(vmx, v);
            vmn = fminf(vmn, v);
            mv  = fmaxf(mv, m);
        } else {
            anyz = 1.0f;
        }
    }
    rS[grp][h] = s;    rQ[grp][h] = ss;
    rMx[grp][h] = vmx; rMn[grp][h] = vmn;
    rMv[grp][h] = mv;  rZ[grp][h] = anyz;
    __syncthreads();

    if (tid < Hn) {
        float sum = rS[0][tid] + rS[1][tid] + rS[2][tid] + rS[3][tid];
        float sq  = rQ[0][tid] + rQ[1][tid] + rQ[2][tid] + rQ[3][tid];
        float mx  = fmaxf(fmaxf(rMx[0][tid], rMx[1][tid]),
                          fmaxf(rMx[2][tid], rMx[3][tid]));
        float mn  = fminf(fminf(rMn[0][tid], rMn[1][tid]),
                          fminf(rMn[2][tid], rMn[3][tid]));
        float m   = fmaxf(fmaxf(rMv[0][tid], rMv[1][tid]),
                          fmaxf(rMv[2][tid], rMv[3][tid]));
        float z   = fmaxf(fmaxf(rZ[0][tid], rZ[1][tid]),
                          fmaxf(rZ[2][tid], rZ[3][tid]));
        float mean = sum * (1.0f / Bn);
        float var  = sq * (1.0f / Bn) - mean * mean;
        float rstd = rsqrtf(var + 1e-5f);
        float sc   = rstd * gamma[tid];
        float sh   = beta[tid] - mean * sc;

        float p;
        if (mx == -FLT_MAX) {
            p = 0.0f;
        } else {
            float vstar = (sc >= 0.0f) ? mx : mn;
            p = m * (vstar * sc + sh);
            if (z > 0.0f) p = fmaxf(p, 0.0f);
        }
        pooled[tid] = p;
    }
    __syncthreads();

    if (tid < OUTn) {
        const float* w = W_fc + tid * (Hn + OUTn);
        float acc = b_fc[tid];
#pragma unroll
        for (int k = 0; k < Hn; k++) acc += pooled[k] * w[k];
#pragma unroll
        for (int k = 0; k < OUTn; k++) acc += pg[t * OUTn + k] * w[Hn + k];
        out[t * OUTn + tid] = acc;
    }
}

// ============================================================================
// Launch
// ============================================================================
extern "C" void kernel_launch(void* const* d_in, const int* in_sizes, int n_in,
                              void* d_out, int out_size) {
    const float* x      = (const float*)d_in[0];
    const float* pg     = (const float*)d_in[1];
    const float* W_ih   = (const float*)d_in[2];
    const float* W_hh   = (const float*)d_in[3];
    const float* b_ih   = (const float*)d_in[4];
    const float* b_hh   = (const float*)d_in[5];
    const float* gamma  = (const float*)d_in[6];
    const float* beta   = (const float*)d_in[7];
    const float* W_fc   = (const float*)d_in[8];
    const float* b_fc   = (const float*)d_in[9];
    const float* dmask  = (const float*)d_in[10];
    float* out = (float*)d_out;

    xw_kernel<<<Tn, 256>>>(x, W_ih, b_ih, b_hh);
    lstm_kernel<<<Bn / BPC, 512>>>(W_hh);
    bn_pool_fc_kernel<<<Tn, 256>>>(pg, gamma, beta, W_fc, b_fc, dmask, out);
}